// round 15
// baseline (speedup 1.0000x reference)
#include <cuda_runtime.h>
#include <cuda_bf16.h>
#include <cstdint>

#define NMAX 100000
#define EMAX 3200000

// Scratch (device globals: allocation is forbidden).
__device__ float g_deg[NMAX];
__device__ float g_dis[NMAX];
__device__ float g_xs[NMAX];
__device__ int   g_cnt[NMAX];
__device__ int   g_rs[NMAX + 1];
__device__ int   g_cur[NMAX];
__device__ unsigned long long g_sstate[128];
__device__ uint2 g_edges[EMAX];         // {src, ea} sorted by dst
__device__ float g_bufA[NMAX * 64];     // layer-1 out (N*16) -> later part (N*2)
__device__ float g_bufB[NMAX * 64];     // layer-2 out (N*32) -> later zprop (N*4)
__device__ float g_t1[NMAX * 64];
__device__ float g_t1s[NMAX];
__device__ float g_t2[NMAX * 64];       // zpack (N*4)
__device__ __nv_bfloat16 g_xb[NMAX * 32];   // bf16 shadow (dis-scaled)
__device__ __nv_bfloat16 g_tb[NMAX * 32];   // bf16 shadow of t1 (dis-scaled)
__device__ unsigned g_wbt3[64 * 96];        // W3 as Bt[co][k], tf32 bits
__device__ unsigned g_wbt2[32 * 48];        // W2 as Bt[co][k], tf32 bits

static inline int cdiv(long long a, int b) { return (int)((a + b - 1) / b); }

__device__ __forceinline__ unsigned to_tf32(float v) {
    unsigned u;
    asm("cvt.rna.tf32.f32 %0, %1;" : "=r"(u) : "f"(v));
    return u;
}

// ===========================================================================
// Build phase (zero + weight prep fused)
// ===========================================================================
__global__ void build_init_k(float* deg, int* cnt, unsigned long long* sstate,
                             const float* __restrict__ W3, const float* __restrict__ W2,
                             unsigned* __restrict__ wbt3, unsigned* __restrict__ wbt2,
                             int n) {
    int i = blockIdx.x * blockDim.x + threadIdx.x;
    if (i < n) { deg[i] = 0.f; cnt[i] = 0; }
    if (i < 128) sstate[i] = 0ULL;
    if (i < 64 * 96) {
        int co = i / 96, k = i % 96;
        wbt3[i] = to_tf32(W3[(k >> 5) * 2048 + (k & 31) * 64 + co]);
    }
    if (i < 32 * 48) {
        int co = i / 48, k = i % 48;
        wbt2[i] = to_tf32(W2[(k >> 4) * 512 + (k & 15) * 32 + co]);
    }
}

__global__ void deg_hist_k(const int* __restrict__ src, const int* __restrict__ dst,
                           const float* __restrict__ ea,
                           float* __restrict__ deg, int* __restrict__ cnt, int E) {
    int base = (blockIdx.x * blockDim.x + threadIdx.x) * 4;
    if (base + 3 < E) {
        int4 s = *reinterpret_cast<const int4*>(src + base);
        int4 d = *reinterpret_cast<const int4*>(dst + base);
        float4 w = *reinterpret_cast<const float4*>(ea + base);
        atomicAdd(&deg[s.x], w.x);
        atomicAdd(&deg[s.y], w.y);
        atomicAdd(&deg[s.z], w.z);
        atomicAdd(&deg[s.w], w.w);
        atomicAdd(&cnt[d.x], 1);
        atomicAdd(&cnt[d.y], 1);
        atomicAdd(&cnt[d.z], 1);
        atomicAdd(&cnt[d.w], 1);
    } else {
        for (int e = base; e < E; e++) {
            atomicAdd(&deg[src[e]], ea[e]);
            atomicAdd(&cnt[dst[e]], 1);
        }
    }
}

__global__ void dis_k(const float* __restrict__ deg, const float* __restrict__ x,
                      float* __restrict__ dis, float* __restrict__ xs, int n) {
    int i = blockIdx.x * blockDim.x + threadIdx.x;
    if (i >= n) return;
    float d = deg[i];
    float r = d > 0.f ? rsqrtf(d) : 0.f;
    dis[i] = r;
    xs[i] = r * x[i];
}

#define SCAN_TPB 256
#define SCAN_ELEMS 1024

__global__ void scan_lookback_k(const int* __restrict__ cnt,
                                unsigned long long* __restrict__ sstate,
                                int* __restrict__ rs, int* __restrict__ cur, int n) {
    int b = blockIdx.x;
    int base = b * SCAN_ELEMS + threadIdx.x * 4;
    int c0 = 0, c1 = 0, c2 = 0, c3 = 0;
    if (base + 3 < n) {
        int4 v = *reinterpret_cast<const int4*>(cnt + base);
        c0 = v.x; c1 = v.y; c2 = v.z; c3 = v.w;
    } else {
        if (base + 0 < n) c0 = cnt[base + 0];
        if (base + 1 < n) c1 = cnt[base + 1];
        if (base + 2 < n) c2 = cnt[base + 2];
        if (base + 3 < n) c3 = cnt[base + 3];
    }
    int ts = c0 + c1 + c2 + c3;
    int lane = threadIdx.x & 31, wid = threadIdx.x >> 5;
    int inc = ts;
#pragma unroll
    for (int o = 1; o < 32; o <<= 1) {
        int v = __shfl_up_sync(0xffffffffu, inc, o);
        if (lane >= o) inc += v;
    }
    __shared__ int wsum[SCAN_TPB / 32];
    __shared__ int woff[SCAN_TPB / 32];
    __shared__ int s_base;
    __shared__ int s_total;
    if (lane == 31) wsum[wid] = inc;
    __syncthreads();
    if (threadIdx.x == 0) {
        int r = 0;
#pragma unroll
        for (int w = 0; w < SCAN_TPB / 32; w++) { woff[w] = r; r += wsum[w]; }
        s_total = r;
        atomicExch(&sstate[b], (1ULL << 62) | (unsigned)r);
        int excl = 0;
        for (int p = b - 1; p >= 0; ) {
            unsigned long long s;
            do { s = atomicAdd(&sstate[p], 0ULL); } while ((s >> 62) == 0);
            excl += (int)(unsigned)s;
            if ((s >> 62) == 2ULL) break;
            p--;
        }
        atomicExch(&sstate[b], (2ULL << 62) | (unsigned)(excl + r));
        s_base = excl;
    }
    __syncthreads();
    int r = s_base + (inc - ts) + woff[wid];
    if (base + 0 < n) { rs[base + 0] = r; cur[base + 0] = r; r += c0; }
    if (base + 1 < n) { rs[base + 1] = r; cur[base + 1] = r; r += c1; }
    if (base + 2 < n) { rs[base + 2] = r; cur[base + 2] = r; r += c2; }
    if (base + 3 < n) { rs[base + 3] = r; cur[base + 3] = r; r += c3; }
    if (b == gridDim.x - 1 && threadIdx.x == 0) rs[n] = s_base + s_total;
}

// 1 edge/thread (measured best)
__global__ void scatter_k(const int* __restrict__ src, const int* __restrict__ dst,
                          const float* __restrict__ ea,
                          int* __restrict__ cur, uint2* __restrict__ ed, int E) {
    int e = blockIdx.x * blockDim.x + threadIdx.x;
    if (e >= E) return;
    int d = dst[e];
    int slot = atomicAdd(&cur[d], 1);
    ed[slot] = make_uint2((unsigned)src[e], __float_as_uint(ea[e]));
}

// ===========================================================================
// Layer 1
// ===========================================================================
__global__ void prop_c1_p1(const float* __restrict__ xs, const float* __restrict__ dis,
                           const uint2* __restrict__ ed, const int* __restrict__ rs,
                           float* __restrict__ out, float* __restrict__ outs, int N) {
    int warp = (blockIdx.x * blockDim.x + threadIdx.x) >> 5;
    int lane = threadIdx.x & 31;
    if (warp >= N) return;
    int beg = rs[warp], end = rs[warp + 1];
    float acc = 0.f;
    for (int j = beg + lane; j < end; j += 32) {
        uint2 e = ed[j];
        acc += __uint_as_float(e.y) * __ldg(xs + e.x);
    }
#pragma unroll
    for (int off = 16; off > 0; off >>= 1)
        acc += __shfl_down_sync(0xffffffffu, acc, off);
    if (lane == 0) {
        float di = dis[warp];
        float r = -di * acc;
        out[warp] = r;
        outs[warp] = di * r;
    }
}

__global__ void fused_l1(const float* __restrict__ t1s, const float* __restrict__ x,
                         const float* __restrict__ t1, const float* __restrict__ dis,
                         const float* __restrict__ W,
                         float* __restrict__ out, __nv_bfloat16* __restrict__ outb,
                         const uint2* __restrict__ ed, const int* __restrict__ rs, int N) {
    __shared__ float sW[48];
    if (threadIdx.x < 48) sW[threadIdx.x] = W[threadIdx.x];
    __syncthreads();
    int warp = (blockIdx.x * blockDim.x + threadIdx.x) >> 5;
    int lane = threadIdx.x & 31;
    if (warp >= N) return;
    int beg = rs[warp], end = rs[warp + 1];
    float acc = 0.f;
    for (int j = beg + lane; j < end; j += 32) {
        uint2 e = ed[j];
        acc += __uint_as_float(e.y) * __ldg(t1s + e.x);
    }
#pragma unroll
    for (int off = 16; off > 0; off >>= 1)
        acc += __shfl_xor_sync(0xffffffffu, acc, off);
    float di = dis[warp];
    float t2v = -di * acc;
    float a = x[warp];
    float b = t1[warp];
    if (lane < 16) {
        float d = 2.f * t2v - a;
        float r = fmaxf(a * sW[lane] + b * sW[16 + lane] + d * sW[32 + lane], 0.f);
        out[(size_t)warp * 16 + lane] = r;
        outb[(size_t)warp * 16 + lane] = __float2bfloat16_rn(di * r);
    }
}

// ===========================================================================
// Pipelined gather bodies (macros to share across pass-1 and fused kernels)
// c16: grp=lane>>3 (4 slots), sub=lane&7.  c32: grp=lane>>4 (2 slots), sub=lane&15.
// ===========================================================================
#define GATHER_C16_PIPE(tbp, beg, end, grp, sub, ax, ay)                        \
    do {                                                                        \
        int j = (beg);                                                          \
        uint2 e[4];                                                             \
        bool have = (j + 16 <= (end));                                          \
        if (have) {                                                             \
            _Pragma("unroll")                                                   \
            for (int k = 0; k < 4; k++) e[k] = ed[j + k * 4 + (grp)];           \
        }                                                                       \
        while (have) {                                                          \
            float2 f[4];                                                        \
            _Pragma("unroll")                                                   \
            for (int k = 0; k < 4; k++) {                                       \
                __nv_bfloat162 v = *reinterpret_cast<const __nv_bfloat162*>(    \
                    (tbp) + (size_t)e[k].x * 16 + (sub) * 2);                   \
                f[k] = __bfloat1622float2(v);                                   \
            }                                                                   \
            int jn = j + 16;                                                    \
            bool haveN = (jn + 16 <= (end));                                    \
            uint2 en[4];                                                        \
            if (haveN) {                                                        \
                _Pragma("unroll")                                               \
                for (int k = 0; k < 4; k++) en[k] = ed[jn + k * 4 + (grp)];     \
            }                                                                   \
            _Pragma("unroll")                                                   \
            for (int k = 0; k < 4; k++) {                                       \
                float w = __uint_as_float(e[k].y);                              \
                ax = fmaf(w, f[k].x, ax);                                       \
                ay = fmaf(w, f[k].y, ay);                                       \
            }                                                                   \
            _Pragma("unroll")                                                   \
            for (int k = 0; k < 4; k++) e[k] = en[k];                           \
            j = jn; have = haveN;                                               \
        }                                                                       \
        for (; j < (end); j += 4) {                                             \
            int idx = j + (grp);                                                \
            if (idx < (end)) {                                                  \
                uint2 ee = ed[idx];                                             \
                __nv_bfloat162 v = *reinterpret_cast<const __nv_bfloat162*>(    \
                    (tbp) + (size_t)ee.x * 16 + (sub) * 2);                     \
                float2 ff = __bfloat1622float2(v);                              \
                float w = __uint_as_float(ee.y);                                \
                ax = fmaf(w, ff.x, ax); ay = fmaf(w, ff.y, ay);                 \
            }                                                                   \
        }                                                                       \
    } while (0)

#define GATHER_C32_PIPE(tbp, beg, end, grp, sub, ax, ay)                        \
    do {                                                                        \
        int j = (beg);                                                          \
        uint2 e[8];                                                             \
        bool have = (j + 16 <= (end));                                          \
        if (have) {                                                             \
            _Pragma("unroll")                                                   \
            for (int k = 0; k < 8; k++) e[k] = ed[j + k * 2 + (grp)];           \
        }                                                                       \
        while (have) {                                                          \
            float2 f[8];                                                        \
            _Pragma("unroll")                                                   \
            for (int k = 0; k < 8; k++) {                                       \
                __nv_bfloat162 v = *reinterpret_cast<const __nv_bfloat162*>(    \
                    (tbp) + (size_t)e[k].x * 32 + (sub) * 2);                   \
                f[k] = __bfloat1622float2(v);                                   \
            }                                                                   \
            int jn = j + 16;                                                    \
            bool haveN = (jn + 16 <= (end));                                    \
            uint2 en[8];                                                        \
            if (haveN) {                                                        \
                _Pragma("unroll")                                               \
                for (int k = 0; k < 8; k++) en[k] = ed[jn + k * 2 + (grp)];     \
            }                                                                   \
            _Pragma("unroll")                                                   \
            for (int k = 0; k < 8; k++) {                                       \
                float w = __uint_as_float(e[k].y);                              \
                ax = fmaf(w, f[k].x, ax);                                       \
                ay = fmaf(w, f[k].y, ay);                                       \
            }                                                                   \
            _Pragma("unroll")                                                   \
            for (int k = 0; k < 8; k++) e[k] = en[k];                           \
            j = jn; have = haveN;                                               \
        }                                                                       \
        for (; j < (end); j += 2) {                                             \
            int idx = j + (grp);                                                \
            if (idx < (end)) {                                                  \
                uint2 ee = ed[idx];                                             \
                __nv_bfloat162 v = *reinterpret_cast<const __nv_bfloat162*>(    \
                    (tbp) + (size_t)ee.x * 32 + (sub) * 2);                     \
                float2 ff = __bfloat1622float2(v);                              \
                float w = __uint_as_float(ee.y);                                \
                ax = fmaf(w, ff.x, ax); ay = fmaf(w, ff.y, ay);                 \
            }                                                                   \
        }                                                                       \
    } while (0)

// ===========================================================================
// Layer 2/3 pass-1 props (pipelined)
// ===========================================================================
__global__ void prop_c16_p1(const __nv_bfloat16* __restrict__ xb,
                            const float* __restrict__ dis,
                            const uint2* __restrict__ ed, const int* __restrict__ rs,
                            float* __restrict__ out, __nv_bfloat16* __restrict__ outb,
                            int N) {
    int warp = (blockIdx.x * blockDim.x + threadIdx.x) >> 5;
    int lane = threadIdx.x & 31;
    if (warp >= N) return;
    int grp = lane >> 3;
    int sub = lane & 7;
    int beg = rs[warp], end = rs[warp + 1];
    float ax = 0.f, ay = 0.f;
    GATHER_C16_PIPE(xb, beg, end, grp, sub, ax, ay);
    ax += __shfl_xor_sync(0xffffffffu, ax, 8);
    ay += __shfl_xor_sync(0xffffffffu, ay, 8);
    ax += __shfl_xor_sync(0xffffffffu, ax, 16);
    ay += __shfl_xor_sync(0xffffffffu, ay, 16);
    if (lane < 8) {
        float di = dis[warp];
        float2 r; r.x = -di * ax; r.y = -di * ay;
        *reinterpret_cast<float2*>(out + (size_t)warp * 16 + sub * 2) = r;
        float2 s; s.x = di * r.x; s.y = di * r.y;
        __nv_bfloat162 b = __float22bfloat162_rn(s);
        *reinterpret_cast<__nv_bfloat162*>(outb + (size_t)warp * 16 + sub * 2) = b;
    }
}

__global__ void prop_c32_p1(const __nv_bfloat16* __restrict__ xb,
                            const float* __restrict__ dis,
                            const uint2* __restrict__ ed, const int* __restrict__ rs,
                            float* __restrict__ out, __nv_bfloat16* __restrict__ outb,
                            int N) {
    int warp = (blockIdx.x * blockDim.x + threadIdx.x) >> 5;
    int lane = threadIdx.x & 31;
    if (warp >= N) return;
    int grp = lane >> 4;
    int sub = lane & 15;
    int beg = rs[warp], end = rs[warp + 1];
    float ax = 0.f, ay = 0.f;
    GATHER_C32_PIPE(xb, beg, end, grp, sub, ax, ay);
    ax += __shfl_xor_sync(0xffffffffu, ax, 16);
    ay += __shfl_xor_sync(0xffffffffu, ay, 16);
    if (lane < 16) {
        float di = dis[warp];
        float2 r; r.x = -di * ax; r.y = -di * ay;
        *reinterpret_cast<float2*>(out + (size_t)warp * 32 + sub * 2) = r;
        float2 s; s.x = di * r.x; s.y = di * r.y;
        __nv_bfloat162 b = __float22bfloat162_rn(s);
        *reinterpret_cast<__nv_bfloat162*>(outb + (size_t)warp * 32 + sub * 2) = b;
    }
}

// ===========================================================================
// Layer 2 fused: pass-2 gather + combine 16->32 via tf32 mma.
// ===========================================================================
#define AS2 52

__global__ void __launch_bounds__(512)
fused_l2_mma(const __nv_bfloat16* __restrict__ tb,
             const float* __restrict__ f0, const float* __restrict__ t1,
             const float* __restrict__ dis, const unsigned* __restrict__ wbt2,
             float* __restrict__ out, __nv_bfloat16* __restrict__ outb,
             const uint2* __restrict__ ed, const int* __restrict__ rs, int N) {
    __shared__ unsigned A_sm[16 * AS2];
    __shared__ unsigned Bt_sm[32 * AS2];
    __shared__ float h_sm[16 * 32];
    __shared__ float dis_sm[16];

    int tid = threadIdx.x;
    int wid = tid >> 5;
    int lane = tid & 31;
    int node = blockIdx.x * 16 + wid;

    for (int i = tid; i < 32 * 48; i += 512) {
        int co = i / 48, k = i % 48;
        Bt_sm[co * AS2 + k] = wbt2[i];
    }

    float di = 0.f;
    float t2x = 0.f, t2y = 0.f;
    if (node < N) {
        int grp = lane >> 3;
        int sub = lane & 7;
        int beg = rs[node], end = rs[node + 1];
        float ax = 0.f, ay = 0.f;
        GATHER_C16_PIPE(tb, beg, end, grp, sub, ax, ay);
        ax += __shfl_xor_sync(0xffffffffu, ax, 8);
        ay += __shfl_xor_sync(0xffffffffu, ay, 8);
        ax += __shfl_xor_sync(0xffffffffu, ax, 16);
        ay += __shfl_xor_sync(0xffffffffu, ay, 16);
        di = dis[node];
        t2x = -di * ax;
        t2y = -di * ay;
    }
    if (lane == 0) dis_sm[wid] = di;

    {
        int c = lane & 15;
        float a = 0.f, b = 0.f, dval = 0.f;
        if (node < N) {
            a = f0[(size_t)node * 16 + c];
            b = t1[(size_t)node * 16 + c];
            float tx = __shfl_sync(0xffffffffu, t2x, c >> 1);
            float ty = __shfl_sync(0xffffffffu, t2y, c >> 1);
            float t2c = (c & 1) ? ty : tx;
            dval = 2.f * t2c - a;
        }
        if (lane < 16) {
            A_sm[wid * AS2 + c] = to_tf32(a);
            A_sm[wid * AS2 + 16 + c] = to_tf32(b);
            A_sm[wid * AS2 + 32 + c] = to_tf32(dval);
        }
    }
    __syncthreads();

    if (wid < 4) {
        int row = lane >> 2;
        int qc = lane & 3;
        float c0 = 0.f, c1 = 0.f, c2 = 0.f, c3 = 0.f;
        const unsigned* Arow0 = A_sm + row * AS2;
        const unsigned* Arow1 = A_sm + (row + 8) * AS2;
        const unsigned* Brow = Bt_sm + (wid * 8 + row) * AS2;
#pragma unroll
        for (int kt = 0; kt < 6; kt++) {
            int k0 = kt * 8 + qc;
            unsigned a0 = Arow0[k0];
            unsigned a1 = Arow1[k0];
            unsigned a2 = Arow0[k0 + 4];
            unsigned a3 = Arow1[k0 + 4];
            unsigned b0 = Brow[k0];
            unsigned b1 = Brow[k0 + 4];
            asm volatile(
                "mma.sync.aligned.m16n8k8.row.col.f32.tf32.tf32.f32 "
                "{%0,%1,%2,%3}, {%4,%5,%6,%7}, {%8,%9}, {%0,%1,%2,%3};"
                : "+f"(c0), "+f"(c1), "+f"(c2), "+f"(c3)
                : "r"(a0), "r"(a1), "r"(a2), "r"(a3), "r"(b0), "r"(b1));
        }
        int col0 = wid * 8 + qc * 2;
        float2 v;
        v.x = fmaxf(c0, 0.f); v.y = fmaxf(c1, 0.f);
        *reinterpret_cast<float2*>(h_sm + row * 32 + col0) = v;
        v.x = fmaxf(c2, 0.f); v.y = fmaxf(c3, 0.f);
        *reinterpret_cast<float2*>(h_sm + (row + 8) * 32 + col0) = v;
    }
    __syncthreads();

    if (node >= N) return;
    float dw = dis_sm[wid];
    float h = h_sm[wid * 32 + lane];
    out[(size_t)node * 32 + lane] = h;
    outb[(size_t)node * 32 + lane] = __float2bfloat16_rn(dw * h);
}

// ===========================================================================
// Layer 3 fused: pass-2 gather + combine via tf32 mma + head GEMM.
// ===========================================================================
#define AS 100

__global__ void __launch_bounds__(512)
fused_l3_mma(const __nv_bfloat16* __restrict__ tb,
             const float* __restrict__ f0, const float* __restrict__ t1,
             const float* __restrict__ dis,
             const unsigned* __restrict__ wbt, const float* __restrict__ W4,
             float* __restrict__ part, float* __restrict__ zpack,
             const uint2* __restrict__ ed, const int* __restrict__ rs, int N) {
    __shared__ unsigned A_sm[16 * AS];
    __shared__ unsigned Bt_sm[64 * AS];
    __shared__ float h_sm[16 * 64];
    __shared__ float sW4[6 * 64];

    int tid = threadIdx.x;
    int wid = tid >> 5;
    int lane = tid & 31;
    int node = blockIdx.x * 16 + wid;

    for (int i = tid; i < 64 * 96; i += 512) {
        int co = i / 96, k = i % 96;
        Bt_sm[co * AS + k] = wbt[i];
    }
    for (int i = tid; i < 384; i += 512) {
        int k = i / 128, rem = i % 128, ci = rem / 2, co = rem % 2;
        sW4[(k * 2 + co) * 64 + ci] = W4[i];
    }

    float di = 0.f, a = 0.f, b = 0.f, dval = 0.f;
    if (node < N) {
        int grp = lane >> 4;
        int sub = lane & 15;
        int beg = rs[node], end = rs[node + 1];
        float ax = 0.f, ay = 0.f;
        GATHER_C32_PIPE(tb, beg, end, grp, sub, ax, ay);
        ax += __shfl_xor_sync(0xffffffffu, ax, 16);
        ay += __shfl_xor_sync(0xffffffffu, ay, 16);
        di = dis[node];
        float t2x = -di * ax;
        float t2y = -di * ay;
        float tx = __shfl_sync(0xffffffffu, t2x, lane >> 1);
        float ty = __shfl_sync(0xffffffffu, t2y, lane >> 1);
        float t2c = (lane & 1) ? ty : tx;
        a = f0[(size_t)node * 32 + lane];
        b = t1[(size_t)node * 32 + lane];
        dval = 2.f * t2c - a;
    }
    A_sm[wid * AS + lane] = to_tf32(a);
    A_sm[wid * AS + 32 + lane] = to_tf32(b);
    A_sm[wid * AS + 64 + lane] = to_tf32(dval);
    __syncthreads();

    if (wid < 8) {
        int row = lane >> 2;
        int qc = lane & 3;
        float c0 = 0.f, c1 = 0.f, c2 = 0.f, c3 = 0.f;
        const unsigned* Arow0 = A_sm + row * AS;
        const unsigned* Arow1 = A_sm + (row + 8) * AS;
        const unsigned* Brow = Bt_sm + (wid * 8 + row) * AS;
#pragma unroll
        for (int kt = 0; kt < 12; kt++) {
            int k0 = kt * 8 + qc;
            unsigned a0 = Arow0[k0];
            unsigned a1 = Arow1[k0];
            unsigned a2 = Arow0[k0 + 4];
            unsigned a3 = Arow1[k0 + 4];
            unsigned b0 = Brow[k0];
            unsigned b1 = Brow[k0 + 4];
            asm volatile(
                "mma.sync.aligned.m16n8k8.row.col.f32.tf32.tf32.f32 "
                "{%0,%1,%2,%3}, {%4,%5,%6,%7}, {%8,%9}, {%0,%1,%2,%3};"
                : "+f"(c0), "+f"(c1), "+f"(c2), "+f"(c3)
                : "r"(a0), "r"(a1), "r"(a2), "r"(a3), "r"(b0), "r"(b1));
        }
        int col0 = wid * 8 + qc * 2;
        float2 v;
        v.x = fmaxf(c0, 0.f); v.y = fmaxf(c1, 0.f);
        *reinterpret_cast<float2*>(h_sm + row * 64 + col0) = v;
        v.x = fmaxf(c2, 0.f); v.y = fmaxf(c3, 0.f);
        *reinterpret_cast<float2*>(h_sm + (row + 8) * 64 + col0) = v;
    }
    __syncthreads();

    if (node >= N) return;
    float h0 = h_sm[wid * 64 + lane];
    float h1 = h_sm[wid * 64 + lane + 32];
    float r[6];
#pragma unroll
    for (int m = 0; m < 6; m++) {
        const float* w = sW4 + m * 64;
        float racc = fmaf(h1, w[lane + 32], h0 * w[lane]);
#pragma unroll
        for (int off = 16; off > 0; off >>= 1)
            racc += __shfl_down_sync(0xffffffffu, racc, off);
        r[m] = racc;
    }
    if (lane == 0) {
        part[(size_t)node * 2 + 0] = r[0] - r[4];
        part[(size_t)node * 2 + 1] = r[1] - r[5];
        float4 z; z.x = di * r[2]; z.y = di * r[3]; z.z = di * r[4]; z.w = di * r[5];
        *reinterpret_cast<float4*>(zpack + (size_t)node * 4) = z;
    }
}

// ===========================================================================
// Layer-4 tail props (batched record+feature loads, MLP 2)
// ===========================================================================
__global__ void prop_csr_c4(const float* __restrict__ zs, const float* __restrict__ dis,
                            const uint2* __restrict__ ed, const int* __restrict__ rs,
                            float* __restrict__ out, int N) {
    int warp = (blockIdx.x * blockDim.x + threadIdx.x) >> 5;
    int lane = threadIdx.x & 31;
    if (warp >= N) return;
    int k = lane >> 2;
    int c = lane & 3;
    int beg = rs[warp], end = rs[warp + 1];
    float acc = 0.f;
    int j = beg + k;
    for (; j + 8 < end; j += 16) {
        uint2 e0 = ed[j];
        uint2 e1 = ed[j + 8];
        float v0 = __ldg(zs + (size_t)e0.x * 4 + c);
        float v1 = __ldg(zs + (size_t)e1.x * 4 + c);
        acc = fmaf(__uint_as_float(e0.y), v0, acc);
        acc = fmaf(__uint_as_float(e1.y), v1, acc);
    }
    if (j < end) {
        uint2 e = ed[j];
        acc = fmaf(__uint_as_float(e.y), __ldg(zs + (size_t)e.x * 4 + c), acc);
    }
#pragma unroll
    for (int off = 16; off >= 4; off >>= 1)
        acc += __shfl_down_sync(0xffffffffu, acc, off);
    if (lane < 4) {
        float di = dis[warp];
        float r = -di * acc;
        out[(size_t)warp * 4 + c] = (c < 2) ? r : di * r;
    }
}

__global__ void prop2_final_k(const float* __restrict__ t4, const float* __restrict__ part,
                              const float* __restrict__ dis,
                              const uint2* __restrict__ ed, const int* __restrict__ rs,
                              float* __restrict__ y, int N) {
    int warp = (blockIdx.x * blockDim.x + threadIdx.x) >> 5;
    int lane = threadIdx.x & 31;
    if (warp >= N) return;
    int k = lane >> 1;
    int c = lane & 1;
    int beg = rs[warp], end = rs[warp + 1];
    float acc = 0.f;
    int j = beg + k;
    for (; j + 16 < end; j += 32) {
        uint2 e0 = ed[j];
        uint2 e1 = ed[j + 16];
        float v0 = __ldg(t4 + (size_t)e0.x * 4 + 2 + c);
        float v1 = __ldg(t4 + (size_t)e1.x * 4 + 2 + c);
        acc = fmaf(__uint_as_float(e0.y), v0, acc);
        acc = fmaf(__uint_as_float(e1.y), v1, acc);
    }
    if (j < end) {
        uint2 e = ed[j];
        acc = fmaf(__uint_as_float(e.y), __ldg(t4 + (size_t)e.x * 4 + 2 + c), acc);
    }
#pragma unroll
    for (int off = 16; off >= 2; off >>= 1)
        acc += __shfl_down_sync(0xffffffffu, acc, off);
    if (lane < 2) {
        float w = -dis[warp] * acc;
        y[(size_t)warp * 2 + c] = part[(size_t)warp * 2 + c]
                                + t4[(size_t)warp * 4 + c] + 2.f * w;
    }
}

extern "C" void kernel_launch(void* const* d_in, const int* in_sizes, int n_in,
                              void* d_out, int out_size) {
    const float* x = (const float*)d_in[0];
    const int* edge_index = (const int*)d_in[1];
    const float* ea = (const float*)d_in[2];
    const float* W1 = (const float*)d_in[3];
    const float* W2 = (const float*)d_in[4];
    const float* W3 = (const float*)d_in[5];
    const float* W4 = (const float*)d_in[6];

    const int N = in_sizes[0];
    const int E = in_sizes[2];
    const int* src = edge_index;
    const int* dst = edge_index + E;

    float *deg, *dis, *xs, *bufA, *bufB, *t1, *t1s, *t2;
    int *cnt, *rs, *cur;
    unsigned long long* sstate;
    uint2* edges;
    __nv_bfloat16 *xb, *tb;
    unsigned *wbt3, *wbt2;
    cudaGetSymbolAddress((void**)&deg, g_deg);
    cudaGetSymbolAddress((void**)&dis, g_dis);
    cudaGetSymbolAddress((void**)&xs, g_xs);
    cudaGetSymbolAddress((void**)&cnt, g_cnt);
    cudaGetSymbolAddress((void**)&rs, g_rs);
    cudaGetSymbolAddress((void**)&cur, g_cur);
    cudaGetSymbolAddress((void**)&sstate, g_sstate);
    cudaGetSymbolAddress((void**)&edges, g_edges);
    cudaGetSymbolAddress((void**)&bufA, g_bufA);
    cudaGetSymbolAddress((void**)&bufB, g_bufB);
    cudaGetSymbolAddress((void**)&t1, g_t1);
    cudaGetSymbolAddress((void**)&t1s, g_t1s);
    cudaGetSymbolAddress((void**)&t2, g_t2);
    cudaGetSymbolAddress((void**)&xb, g_xb);
    cudaGetSymbolAddress((void**)&tb, g_tb);
    cudaGetSymbolAddress((void**)&wbt3, g_wbt3);
    cudaGetSymbolAddress((void**)&wbt2, g_wbt2);

    // ---- build CSR + dis + weight prep ----
    build_init_k<<<cdiv(N, 256), 256>>>(deg, cnt, sstate, W3, W2, wbt3, wbt2, N);
    deg_hist_k<<<cdiv(cdiv(E, 4), 256), 256>>>(src, dst, ea, deg, cnt, E);
    int nb = cdiv(N, SCAN_ELEMS);
    scan_lookback_k<<<nb, SCAN_TPB>>>(cnt, sstate, rs, cur, N);
    scatter_k<<<cdiv(E, 256), 256>>>(src, dst, ea, cur, edges, E);
    dis_k<<<cdiv(N, 256), 256>>>(deg, x, dis, xs, N);

    const int WPB = 256;
    int grid_n = cdiv((long long)N * 32, WPB);

    // ---- layer 1 ----
    prop_c1_p1<<<grid_n, WPB>>>(xs, dis, edges, rs, t1, t1s, N);
    fused_l1<<<grid_n, WPB>>>(t1s, x, t1, dis, W1, bufA, xb, edges, rs, N);

    // ---- layer 2 (tf32 mma combine) ----
    prop_c16_p1<<<grid_n, WPB>>>(xb, dis, edges, rs, t1, tb, N);
    fused_l2_mma<<<cdiv(N, 16), 512>>>(tb, bufA, t1, dis, wbt2, bufB, xb, edges, rs, N);

    // ---- layer 3 (tf32 mma combine) + head ----
    prop_c32_p1<<<grid_n, WPB>>>(xb, dis, edges, rs, t1, tb, N);
    fused_l3_mma<<<cdiv(N, 16), 512>>>(tb, bufB, t1, dis, wbt3, W4,
                                       bufA, t2, edges, rs, N);

    // ---- layer 4 tail ----
    prop_csr_c4<<<grid_n, WPB>>>(t2, dis, edges, rs, bufB, N);
    prop2_final_k<<<grid_n, WPB>>>(bufB, bufA, dis, edges, rs, (float*)d_out, N);
}

// round 16
// speedup vs baseline: 1.0828x; 1.0828x over previous
#include <cuda_runtime.h>
#include <cuda_bf16.h>
#include <cstdint>

#define NMAX 100000
#define EMAX 3200000

// Scratch (device globals: allocation is forbidden).
__device__ float g_deg[NMAX];
__device__ float g_dis[NMAX];
__device__ float g_xs[NMAX];
__device__ int   g_cnt[NMAX];
__device__ int   g_rs[NMAX + 1];
__device__ int   g_cur[NMAX];
__device__ unsigned long long g_sstate[128];
__device__ uint2 g_edges[EMAX];         // {src, ea} sorted by dst
__device__ float g_bufA[NMAX * 64];     // layer-1 out (N*16) -> later part (N*2)
__device__ float g_bufB[NMAX * 64];     // layer-2 out (N*32) -> later zprop (N*4)
__device__ float g_t1[NMAX * 64];
__device__ float g_t1s[NMAX];
__device__ float g_t2[NMAX * 64];       // zpack (N*4)
__device__ __nv_bfloat16 g_xb[NMAX * 32];   // bf16 shadow (dis-scaled)
__device__ __nv_bfloat16 g_tb[NMAX * 32];   // bf16 shadow of t1 (dis-scaled)
__device__ unsigned g_wbt3[64 * 96];        // W3 as Bt[co][k], tf32 bits
__device__ unsigned g_wbt2[32 * 48];        // W2 as Bt[co][k], tf32 bits

static inline int cdiv(long long a, int b) { return (int)((a + b - 1) / b); }

__device__ __forceinline__ unsigned to_tf32(float v) {
    unsigned u;
    asm("cvt.rna.tf32.f32 %0, %1;" : "=r"(u) : "f"(v));
    return u;
}

// ===========================================================================
// Build phase (zero + weight prep fused — kept from R15, independent writes)
// ===========================================================================
__global__ void build_init_k(float* deg, int* cnt, unsigned long long* sstate,
                             const float* __restrict__ W3, const float* __restrict__ W2,
                             unsigned* __restrict__ wbt3, unsigned* __restrict__ wbt2,
                             int n) {
    int i = blockIdx.x * blockDim.x + threadIdx.x;
    if (i < n) { deg[i] = 0.f; cnt[i] = 0; }
    if (i < 128) sstate[i] = 0ULL;
    if (i < 64 * 96) {
        int co = i / 96, k = i % 96;
        wbt3[i] = to_tf32(W3[(k >> 5) * 2048 + (k & 31) * 64 + co]);
    }
    if (i < 32 * 48) {
        int co = i / 48, k = i % 48;
        wbt2[i] = to_tf32(W2[(k >> 4) * 512 + (k & 15) * 32 + co]);
    }
}

__global__ void deg_hist_k(const int* __restrict__ src, const int* __restrict__ dst,
                           const float* __restrict__ ea,
                           float* __restrict__ deg, int* __restrict__ cnt, int E) {
    int base = (blockIdx.x * blockDim.x + threadIdx.x) * 4;
    if (base + 3 < E) {
        int4 s = *reinterpret_cast<const int4*>(src + base);
        int4 d = *reinterpret_cast<const int4*>(dst + base);
        float4 w = *reinterpret_cast<const float4*>(ea + base);
        atomicAdd(&deg[s.x], w.x);
        atomicAdd(&deg[s.y], w.y);
        atomicAdd(&deg[s.z], w.z);
        atomicAdd(&deg[s.w], w.w);
        atomicAdd(&cnt[d.x], 1);
        atomicAdd(&cnt[d.y], 1);
        atomicAdd(&cnt[d.z], 1);
        atomicAdd(&cnt[d.w], 1);
    } else {
        for (int e = base; e < E; e++) {
            atomicAdd(&deg[src[e]], ea[e]);
            atomicAdd(&cnt[dst[e]], 1);
        }
    }
}

__global__ void dis_k(const float* __restrict__ deg, const float* __restrict__ x,
                      float* __restrict__ dis, float* __restrict__ xs, int n) {
    int i = blockIdx.x * blockDim.x + threadIdx.x;
    if (i >= n) return;
    float d = deg[i];
    float r = d > 0.f ? rsqrtf(d) : 0.f;
    dis[i] = r;
    xs[i] = r * x[i];
}

#define SCAN_TPB 256
#define SCAN_ELEMS 1024

__global__ void scan_lookback_k(const int* __restrict__ cnt,
                                unsigned long long* __restrict__ sstate,
                                int* __restrict__ rs, int* __restrict__ cur, int n) {
    int b = blockIdx.x;
    int base = b * SCAN_ELEMS + threadIdx.x * 4;
    int c0 = 0, c1 = 0, c2 = 0, c3 = 0;
    if (base + 3 < n) {
        int4 v = *reinterpret_cast<const int4*>(cnt + base);
        c0 = v.x; c1 = v.y; c2 = v.z; c3 = v.w;
    } else {
        if (base + 0 < n) c0 = cnt[base + 0];
        if (base + 1 < n) c1 = cnt[base + 1];
        if (base + 2 < n) c2 = cnt[base + 2];
        if (base + 3 < n) c3 = cnt[base + 3];
    }
    int ts = c0 + c1 + c2 + c3;
    int lane = threadIdx.x & 31, wid = threadIdx.x >> 5;
    int inc = ts;
#pragma unroll
    for (int o = 1; o < 32; o <<= 1) {
        int v = __shfl_up_sync(0xffffffffu, inc, o);
        if (lane >= o) inc += v;
    }
    __shared__ int wsum[SCAN_TPB / 32];
    __shared__ int woff[SCAN_TPB / 32];
    __shared__ int s_base;
    __shared__ int s_total;
    if (lane == 31) wsum[wid] = inc;
    __syncthreads();
    if (threadIdx.x == 0) {
        int r = 0;
#pragma unroll
        for (int w = 0; w < SCAN_TPB / 32; w++) { woff[w] = r; r += wsum[w]; }
        s_total = r;
        atomicExch(&sstate[b], (1ULL << 62) | (unsigned)r);
        int excl = 0;
        for (int p = b - 1; p >= 0; ) {
            unsigned long long s;
            do { s = atomicAdd(&sstate[p], 0ULL); } while ((s >> 62) == 0);
            excl += (int)(unsigned)s;
            if ((s >> 62) == 2ULL) break;
            p--;
        }
        atomicExch(&sstate[b], (2ULL << 62) | (unsigned)(excl + r));
        s_base = excl;
    }
    __syncthreads();
    int r = s_base + (inc - ts) + woff[wid];
    if (base + 0 < n) { rs[base + 0] = r; cur[base + 0] = r; r += c0; }
    if (base + 1 < n) { rs[base + 1] = r; cur[base + 1] = r; r += c1; }
    if (base + 2 < n) { rs[base + 2] = r; cur[base + 2] = r; r += c2; }
    if (base + 3 < n) { rs[base + 3] = r; cur[base + 3] = r; r += c3; }
    if (b == gridDim.x - 1 && threadIdx.x == 0) rs[n] = s_base + s_total;
}

// 1 edge/thread (measured best)
__global__ void scatter_k(const int* __restrict__ src, const int* __restrict__ dst,
                          const float* __restrict__ ea,
                          int* __restrict__ cur, uint2* __restrict__ ed, int E) {
    int e = blockIdx.x * blockDim.x + threadIdx.x;
    if (e >= E) return;
    int d = dst[e];
    int slot = atomicAdd(&cur[d], 1);
    ed[slot] = make_uint2((unsigned)src[e], __float_as_uint(ea[e]));
}

// ===========================================================================
// Layer 1
// ===========================================================================
__global__ void prop_c1_p1(const float* __restrict__ xs, const float* __restrict__ dis,
                           const uint2* __restrict__ ed, const int* __restrict__ rs,
                           float* __restrict__ out, float* __restrict__ outs, int N) {
    int warp = (blockIdx.x * blockDim.x + threadIdx.x) >> 5;
    int lane = threadIdx.x & 31;
    if (warp >= N) return;
    int beg = rs[warp], end = rs[warp + 1];
    float acc = 0.f;
    for (int j = beg + lane; j < end; j += 32) {
        uint2 e = ed[j];
        acc += __uint_as_float(e.y) * __ldg(xs + e.x);
    }
#pragma unroll
    for (int off = 16; off > 0; off >>= 1)
        acc += __shfl_down_sync(0xffffffffu, acc, off);
    if (lane == 0) {
        float di = dis[warp];
        float r = -di * acc;
        out[warp] = r;
        outs[warp] = di * r;
    }
}

__global__ void fused_l1(const float* __restrict__ t1s, const float* __restrict__ x,
                         const float* __restrict__ t1, const float* __restrict__ dis,
                         const float* __restrict__ W,
                         float* __restrict__ out, __nv_bfloat16* __restrict__ outb,
                         const uint2* __restrict__ ed, const int* __restrict__ rs, int N) {
    __shared__ float sW[48];
    if (threadIdx.x < 48) sW[threadIdx.x] = W[threadIdx.x];
    __syncthreads();
    int warp = (blockIdx.x * blockDim.x + threadIdx.x) >> 5;
    int lane = threadIdx.x & 31;
    if (warp >= N) return;
    int beg = rs[warp], end = rs[warp + 1];
    float acc = 0.f;
    for (int j = beg + lane; j < end; j += 32) {
        uint2 e = ed[j];
        acc += __uint_as_float(e.y) * __ldg(t1s + e.x);
    }
#pragma unroll
    for (int off = 16; off > 0; off >>= 1)
        acc += __shfl_xor_sync(0xffffffffu, acc, off);
    float di = dis[warp];
    float t2v = -di * acc;
    float a = x[warp];
    float b = t1[warp];
    if (lane < 16) {
        float d = 2.f * t2v - a;
        float r = fmaxf(a * sW[lane] + b * sW[16 + lane] + d * sW[32 + lane], 0.f);
        out[(size_t)warp * 16 + lane] = r;
        outb[(size_t)warp * 16 + lane] = __float2bfloat16_rn(di * r);
    }
}

// ===========================================================================
// Layer 2/3 pass-1 props (R14 bodies)
// ===========================================================================
__global__ void prop_c16_p1(const __nv_bfloat16* __restrict__ xb,
                            const float* __restrict__ dis,
                            const uint2* __restrict__ ed, const int* __restrict__ rs,
                            float* __restrict__ out, __nv_bfloat16* __restrict__ outb,
                            int N) {
    int warp = (blockIdx.x * blockDim.x + threadIdx.x) >> 5;
    int lane = threadIdx.x & 31;
    if (warp >= N) return;
    int grp = lane >> 3;
    int sub = lane & 7;
    int beg = rs[warp], end = rs[warp + 1];
    float ax = 0.f, ay = 0.f;
    int j = beg;
    for (; j + 16 <= end; j += 16) {
        uint2 e[4];
#pragma unroll
        for (int k = 0; k < 4; k++) e[k] = ed[j + k * 4 + grp];
        float2 f[4];
#pragma unroll
        for (int k = 0; k < 4; k++) {
            __nv_bfloat162 v = *reinterpret_cast<const __nv_bfloat162*>(
                xb + (size_t)e[k].x * 16 + sub * 2);
            f[k] = __bfloat1622float2(v);
        }
#pragma unroll
        for (int k = 0; k < 4; k++) {
            float w = __uint_as_float(e[k].y);
            ax = fmaf(w, f[k].x, ax);
            ay = fmaf(w, f[k].y, ay);
        }
    }
    for (; j < end; j += 4) {
        int idx = j + grp;
        if (idx < end) {
            uint2 e = ed[idx];
            __nv_bfloat162 v = *reinterpret_cast<const __nv_bfloat162*>(
                xb + (size_t)e.x * 16 + sub * 2);
            float2 f = __bfloat1622float2(v);
            float w = __uint_as_float(e.y);
            ax = fmaf(w, f.x, ax); ay = fmaf(w, f.y, ay);
        }
    }
    ax += __shfl_xor_sync(0xffffffffu, ax, 8);
    ay += __shfl_xor_sync(0xffffffffu, ay, 8);
    ax += __shfl_xor_sync(0xffffffffu, ax, 16);
    ay += __shfl_xor_sync(0xffffffffu, ay, 16);
    if (lane < 8) {
        float di = dis[warp];
        float2 r; r.x = -di * ax; r.y = -di * ay;
        *reinterpret_cast<float2*>(out + (size_t)warp * 16 + sub * 2) = r;
        float2 s; s.x = di * r.x; s.y = di * r.y;
        __nv_bfloat162 b = __float22bfloat162_rn(s);
        *reinterpret_cast<__nv_bfloat162*>(outb + (size_t)warp * 16 + sub * 2) = b;
    }
}

__global__ void prop_c32_p1(const __nv_bfloat16* __restrict__ xb,
                            const float* __restrict__ dis,
                            const uint2* __restrict__ ed, const int* __restrict__ rs,
                            float* __restrict__ out, __nv_bfloat16* __restrict__ outb,
                            int N) {
    int warp = (blockIdx.x * blockDim.x + threadIdx.x) >> 5;
    int lane = threadIdx.x & 31;
    if (warp >= N) return;
    int grp = lane >> 4;
    int sub = lane & 15;
    int beg = rs[warp], end = rs[warp + 1];
    float ax = 0.f, ay = 0.f;
    int j = beg;
    for (; j + 16 <= end; j += 16) {
        uint2 e[8];
#pragma unroll
        for (int k = 0; k < 8; k++) e[k] = ed[j + k * 2 + grp];
        float2 f[8];
#pragma unroll
        for (int k = 0; k < 8; k++) {
            __nv_bfloat162 v = *reinterpret_cast<const __nv_bfloat162*>(
                xb + (size_t)e[k].x * 32 + sub * 2);
            f[k] = __bfloat1622float2(v);
        }
#pragma unroll
        for (int k = 0; k < 8; k++) {
            float w = __uint_as_float(e[k].y);
            ax = fmaf(w, f[k].x, ax);
            ay = fmaf(w, f[k].y, ay);
        }
    }
    for (; j < end; j += 2) {
        int idx = j + grp;
        if (idx < end) {
            uint2 e = ed[idx];
            __nv_bfloat162 v = *reinterpret_cast<const __nv_bfloat162*>(
                xb + (size_t)e.x * 32 + sub * 2);
            float2 f = __bfloat1622float2(v);
            float w = __uint_as_float(e.y);
            ax = fmaf(w, f.x, ax); ay = fmaf(w, f.y, ay);
        }
    }
    ax += __shfl_xor_sync(0xffffffffu, ax, 16);
    ay += __shfl_xor_sync(0xffffffffu, ay, 16);
    if (lane < 16) {
        float di = dis[warp];
        float2 r; r.x = -di * ax; r.y = -di * ay;
        *reinterpret_cast<float2*>(out + (size_t)warp * 32 + sub * 2) = r;
        float2 s; s.x = di * r.x; s.y = di * r.y;
        __nv_bfloat162 b = __float22bfloat162_rn(s);
        *reinterpret_cast<__nv_bfloat162*>(outb + (size_t)warp * 32 + sub * 2) = b;
    }
}

// ===========================================================================
// Layer 2 fused: pass-2 gather + combine 16->32 via tf32 mma (R14 body).
// ===========================================================================
#define AS2 52

__global__ void __launch_bounds__(512)
fused_l2_mma(const __nv_bfloat16* __restrict__ tb,
             const float* __restrict__ f0, const float* __restrict__ t1,
             const float* __restrict__ dis, const unsigned* __restrict__ wbt2,
             float* __restrict__ out, __nv_bfloat16* __restrict__ outb,
             const uint2* __restrict__ ed, const int* __restrict__ rs, int N) {
    __shared__ unsigned A_sm[16 * AS2];
    __shared__ unsigned Bt_sm[32 * AS2];
    __shared__ float h_sm[16 * 32];
    __shared__ float dis_sm[16];

    int tid = threadIdx.x;
    int wid = tid >> 5;
    int lane = tid & 31;
    int node = blockIdx.x * 16 + wid;

    for (int i = tid; i < 32 * 48; i += 512) {
        int co = i / 48, k = i % 48;
        Bt_sm[co * AS2 + k] = wbt2[i];
    }

    float di = 0.f;
    float t2x = 0.f, t2y = 0.f;
    if (node < N) {
        int grp = lane >> 3;
        int sub = lane & 7;
        int beg = rs[node], end = rs[node + 1];
        float ax = 0.f, ay = 0.f;
        int j = beg;
        for (; j + 16 <= end; j += 16) {
            uint2 e[4];
#pragma unroll
            for (int k = 0; k < 4; k++) e[k] = ed[j + k * 4 + grp];
            float2 f[4];
#pragma unroll
            for (int k = 0; k < 4; k++) {
                __nv_bfloat162 v = *reinterpret_cast<const __nv_bfloat162*>(
                    tb + (size_t)e[k].x * 16 + sub * 2);
                f[k] = __bfloat1622float2(v);
            }
#pragma unroll
            for (int k = 0; k < 4; k++) {
                float w = __uint_as_float(e[k].y);
                ax = fmaf(w, f[k].x, ax);
                ay = fmaf(w, f[k].y, ay);
            }
        }
        for (; j < end; j += 4) {
            int idx = j + grp;
            if (idx < end) {
                uint2 e = ed[idx];
                __nv_bfloat162 v = *reinterpret_cast<const __nv_bfloat162*>(
                    tb + (size_t)e.x * 16 + sub * 2);
                float2 f = __bfloat1622float2(v);
                float w = __uint_as_float(e.y);
                ax = fmaf(w, f.x, ax); ay = fmaf(w, f.y, ay);
            }
        }
        ax += __shfl_xor_sync(0xffffffffu, ax, 8);
        ay += __shfl_xor_sync(0xffffffffu, ay, 8);
        ax += __shfl_xor_sync(0xffffffffu, ax, 16);
        ay += __shfl_xor_sync(0xffffffffu, ay, 16);
        di = dis[node];
        t2x = -di * ax;
        t2y = -di * ay;
    }
    if (lane == 0) dis_sm[wid] = di;

    {
        int c = lane & 15;
        float a = 0.f, b = 0.f, dval = 0.f;
        if (node < N) {
            a = f0[(size_t)node * 16 + c];
            b = t1[(size_t)node * 16 + c];
            float tx = __shfl_sync(0xffffffffu, t2x, c >> 1);
            float ty = __shfl_sync(0xffffffffu, t2y, c >> 1);
            float t2c = (c & 1) ? ty : tx;
            dval = 2.f * t2c - a;
        }
        if (lane < 16) {
            A_sm[wid * AS2 + c] = to_tf32(a);
            A_sm[wid * AS2 + 16 + c] = to_tf32(b);
            A_sm[wid * AS2 + 32 + c] = to_tf32(dval);
        }
    }
    __syncthreads();

    if (wid < 4) {
        int row = lane >> 2;
        int qc = lane & 3;
        float c0 = 0.f, c1 = 0.f, c2 = 0.f, c3 = 0.f;
        const unsigned* Arow0 = A_sm + row * AS2;
        const unsigned* Arow1 = A_sm + (row + 8) * AS2;
        const unsigned* Brow = Bt_sm + (wid * 8 + row) * AS2;
#pragma unroll
        for (int kt = 0; kt < 6; kt++) {
            int k0 = kt * 8 + qc;
            unsigned a0 = Arow0[k0];
            unsigned a1 = Arow1[k0];
            unsigned a2 = Arow0[k0 + 4];
            unsigned a3 = Arow1[k0 + 4];
            unsigned b0 = Brow[k0];
            unsigned b1 = Brow[k0 + 4];
            asm volatile(
                "mma.sync.aligned.m16n8k8.row.col.f32.tf32.tf32.f32 "
                "{%0,%1,%2,%3}, {%4,%5,%6,%7}, {%8,%9}, {%0,%1,%2,%3};"
                : "+f"(c0), "+f"(c1), "+f"(c2), "+f"(c3)
                : "r"(a0), "r"(a1), "r"(a2), "r"(a3), "r"(b0), "r"(b1));
        }
        int col0 = wid * 8 + qc * 2;
        float2 v;
        v.x = fmaxf(c0, 0.f); v.y = fmaxf(c1, 0.f);
        *reinterpret_cast<float2*>(h_sm + row * 32 + col0) = v;
        v.x = fmaxf(c2, 0.f); v.y = fmaxf(c3, 0.f);
        *reinterpret_cast<float2*>(h_sm + (row + 8) * 32 + col0) = v;
    }
    __syncthreads();

    if (node >= N) return;
    float dw = dis_sm[wid];
    float h = h_sm[wid * 32 + lane];
    out[(size_t)node * 32 + lane] = h;
    outb[(size_t)node * 32 + lane] = __float2bfloat16_rn(dw * h);
}

// ===========================================================================
// Layer 3 fused: pass-2 gather + combine via tf32 mma + head GEMM (R14 body).
// ===========================================================================
#define AS 100

__global__ void __launch_bounds__(512)
fused_l3_mma(const __nv_bfloat16* __restrict__ tb,
             const float* __restrict__ f0, const float* __restrict__ t1,
             const float* __restrict__ dis,
             const unsigned* __restrict__ wbt, const float* __restrict__ W4,
             float* __restrict__ part, float* __restrict__ zpack,
             const uint2* __restrict__ ed, const int* __restrict__ rs, int N) {
    __shared__ unsigned A_sm[16 * AS];
    __shared__ unsigned Bt_sm[64 * AS];
    __shared__ float h_sm[16 * 64];
    __shared__ float sW4[6 * 64];

    int tid = threadIdx.x;
    int wid = tid >> 5;
    int lane = tid & 31;
    int node = blockIdx.x * 16 + wid;

    for (int i = tid; i < 64 * 96; i += 512) {
        int co = i / 96, k = i % 96;
        Bt_sm[co * AS + k] = wbt[i];
    }
    for (int i = tid; i < 384; i += 512) {
        int k = i / 128, rem = i % 128, ci = rem / 2, co = rem % 2;
        sW4[(k * 2 + co) * 64 + ci] = W4[i];
    }

    float di = 0.f, a = 0.f, b = 0.f, dval = 0.f;
    if (node < N) {
        int grp = lane >> 4;
        int sub = lane & 15;
        int beg = rs[node], end = rs[node + 1];
        float ax = 0.f, ay = 0.f;
        int j = beg;
        for (; j + 16 <= end; j += 16) {
            uint2 e[8];
#pragma unroll
            for (int k = 0; k < 8; k++) e[k] = ed[j + k * 2 + grp];
            float2 f[8];
#pragma unroll
            for (int k = 0; k < 8; k++) {
                __nv_bfloat162 v = *reinterpret_cast<const __nv_bfloat162*>(
                    tb + (size_t)e[k].x * 32 + sub * 2);
                f[k] = __bfloat1622float2(v);
            }
#pragma unroll
            for (int k = 0; k < 8; k++) {
                float w = __uint_as_float(e[k].y);
                ax = fmaf(w, f[k].x, ax);
                ay = fmaf(w, f[k].y, ay);
            }
        }
        for (; j < end; j += 2) {
            int idx = j + grp;
            if (idx < end) {
                uint2 e = ed[idx];
                __nv_bfloat162 v = *reinterpret_cast<const __nv_bfloat162*>(
                    tb + (size_t)e.x * 32 + sub * 2);
                float2 f = __bfloat1622float2(v);
                float w = __uint_as_float(e.y);
                ax = fmaf(w, f.x, ax); ay = fmaf(w, f.y, ay);
            }
        }
        ax += __shfl_xor_sync(0xffffffffu, ax, 16);
        ay += __shfl_xor_sync(0xffffffffu, ay, 16);
        di = dis[node];
        float t2x = -di * ax;
        float t2y = -di * ay;
        float tx = __shfl_sync(0xffffffffu, t2x, lane >> 1);
        float ty = __shfl_sync(0xffffffffu, t2y, lane >> 1);
        float t2c = (lane & 1) ? ty : tx;
        a = f0[(size_t)node * 32 + lane];
        b = t1[(size_t)node * 32 + lane];
        dval = 2.f * t2c - a;
    }
    A_sm[wid * AS + lane] = to_tf32(a);
    A_sm[wid * AS + 32 + lane] = to_tf32(b);
    A_sm[wid * AS + 64 + lane] = to_tf32(dval);
    __syncthreads();

    if (wid < 8) {
        int row = lane >> 2;
        int qc = lane & 3;
        float c0 = 0.f, c1 = 0.f, c2 = 0.f, c3 = 0.f;
        const unsigned* Arow0 = A_sm + row * AS;
        const unsigned* Arow1 = A_sm + (row + 8) * AS;
        const unsigned* Brow = Bt_sm + (wid * 8 + row) * AS;
#pragma unroll
        for (int kt = 0; kt < 12; kt++) {
            int k0 = kt * 8 + qc;
            unsigned a0 = Arow0[k0];
            unsigned a1 = Arow1[k0];
            unsigned a2 = Arow0[k0 + 4];
            unsigned a3 = Arow1[k0 + 4];
            unsigned b0 = Brow[k0];
            unsigned b1 = Brow[k0 + 4];
            asm volatile(
                "mma.sync.aligned.m16n8k8.row.col.f32.tf32.tf32.f32 "
                "{%0,%1,%2,%3}, {%4,%5,%6,%7}, {%8,%9}, {%0,%1,%2,%3};"
                : "+f"(c0), "+f"(c1), "+f"(c2), "+f"(c3)
                : "r"(a0), "r"(a1), "r"(a2), "r"(a3), "r"(b0), "r"(b1));
        }
        int col0 = wid * 8 + qc * 2;
        float2 v;
        v.x = fmaxf(c0, 0.f); v.y = fmaxf(c1, 0.f);
        *reinterpret_cast<float2*>(h_sm + row * 64 + col0) = v;
        v.x = fmaxf(c2, 0.f); v.y = fmaxf(c3, 0.f);
        *reinterpret_cast<float2*>(h_sm + (row + 8) * 64 + col0) = v;
    }
    __syncthreads();

    if (node >= N) return;
    float h0 = h_sm[wid * 64 + lane];
    float h1 = h_sm[wid * 64 + lane + 32];
    float r[6];
#pragma unroll
    for (int m = 0; m < 6; m++) {
        const float* w = sW4 + m * 64;
        float racc = fmaf(h1, w[lane + 32], h0 * w[lane]);
#pragma unroll
        for (int off = 16; off > 0; off >>= 1)
            racc += __shfl_down_sync(0xffffffffu, racc, off);
        r[m] = racc;
    }
    if (lane == 0) {
        part[(size_t)node * 2 + 0] = r[0] - r[4];
        part[(size_t)node * 2 + 1] = r[1] - r[5];
        float4 z; z.x = di * r[2]; z.y = di * r[3]; z.z = di * r[4]; z.w = di * r[5];
        *reinterpret_cast<float4*>(zpack + (size_t)node * 4) = z;
    }
}

// ===========================================================================
// Layer-4 tail props (R14 bodies)
// ===========================================================================
__global__ void prop_csr_c4(const float* __restrict__ zs, const float* __restrict__ dis,
                            const uint2* __restrict__ ed, const int* __restrict__ rs,
                            float* __restrict__ out, int N) {
    int warp = (blockIdx.x * blockDim.x + threadIdx.x) >> 5;
    int lane = threadIdx.x & 31;
    if (warp >= N) return;
    int k = lane >> 2;
    int c = lane & 3;
    int beg = rs[warp], end = rs[warp + 1];
    float acc = 0.f;
    for (int j = beg + k; j < end; j += 8) {
        uint2 e = ed[j];
        acc = fmaf(__uint_as_float(e.y), __ldg(zs + (size_t)e.x * 4 + c), acc);
    }
#pragma unroll
    for (int off = 16; off >= 4; off >>= 1)
        acc += __shfl_down_sync(0xffffffffu, acc, off);
    if (lane < 4) {
        float di = dis[warp];
        float r = -di * acc;
        out[(size_t)warp * 4 + c] = (c < 2) ? r : di * r;
    }
}

__global__ void prop2_final_k(const float* __restrict__ t4, const float* __restrict__ part,
                              const float* __restrict__ dis,
                              const uint2* __restrict__ ed, const int* __restrict__ rs,
                              float* __restrict__ y, int N) {
    int warp = (blockIdx.x * blockDim.x + threadIdx.x) >> 5;
    int lane = threadIdx.x & 31;
    if (warp >= N) return;
    int k = lane >> 1;
    int c = lane & 1;
    int beg = rs[warp], end = rs[warp + 1];
    float acc = 0.f;
    for (int j = beg + k; j < end; j += 16) {
        uint2 e = ed[j];
        acc = fmaf(__uint_as_float(e.y), __ldg(t4 + (size_t)e.x * 4 + 2 + c), acc);
    }
#pragma unroll
    for (int off = 16; off >= 2; off >>= 1)
        acc += __shfl_down_sync(0xffffffffu, acc, off);
    if (lane < 2) {
        float w = -dis[warp] * acc;
        y[(size_t)warp * 2 + c] = part[(size_t)warp * 2 + c]
                                + t4[(size_t)warp * 4 + c] + 2.f * w;
    }
}

extern "C" void kernel_launch(void* const* d_in, const int* in_sizes, int n_in,
                              void* d_out, int out_size) {
    const float* x = (const float*)d_in[0];
    const int* edge_index = (const int*)d_in[1];
    const float* ea = (const float*)d_in[2];
    const float* W1 = (const float*)d_in[3];
    const float* W2 = (const float*)d_in[4];
    const float* W3 = (const float*)d_in[5];
    const float* W4 = (const float*)d_in[6];

    const int N = in_sizes[0];
    const int E = in_sizes[2];
    const int* src = edge_index;
    const int* dst = edge_index + E;

    float *deg, *dis, *xs, *bufA, *bufB, *t1, *t1s, *t2;
    int *cnt, *rs, *cur;
    unsigned long long* sstate;
    uint2* edges;
    __nv_bfloat16 *xb, *tb;
    unsigned *wbt3, *wbt2;
    cudaGetSymbolAddress((void**)&deg, g_deg);
    cudaGetSymbolAddress((void**)&dis, g_dis);
    cudaGetSymbolAddress((void**)&xs, g_xs);
    cudaGetSymbolAddress((void**)&cnt, g_cnt);
    cudaGetSymbolAddress((void**)&rs, g_rs);
    cudaGetSymbolAddress((void**)&cur, g_cur);
    cudaGetSymbolAddress((void**)&sstate, g_sstate);
    cudaGetSymbolAddress((void**)&edges, g_edges);
    cudaGetSymbolAddress((void**)&bufA, g_bufA);
    cudaGetSymbolAddress((void**)&bufB, g_bufB);
    cudaGetSymbolAddress((void**)&t1, g_t1);
    cudaGetSymbolAddress((void**)&t1s, g_t1s);
    cudaGetSymbolAddress((void**)&t2, g_t2);
    cudaGetSymbolAddress((void**)&xb, g_xb);
    cudaGetSymbolAddress((void**)&tb, g_tb);
    cudaGetSymbolAddress((void**)&wbt3, g_wbt3);
    cudaGetSymbolAddress((void**)&wbt2, g_wbt2);

    // ---- build CSR + dis + weight prep ----
    build_init_k<<<cdiv(N, 256), 256>>>(deg, cnt, sstate, W3, W2, wbt3, wbt2, N);
    deg_hist_k<<<cdiv(cdiv(E, 4), 256), 256>>>(src, dst, ea, deg, cnt, E);
    int nb = cdiv(N, SCAN_ELEMS);
    scan_lookback_k<<<nb, SCAN_TPB>>>(cnt, sstate, rs, cur, N);
    scatter_k<<<cdiv(E, 256), 256>>>(src, dst, ea, cur, edges, E);
    dis_k<<<cdiv(N, 256), 256>>>(deg, x, dis, xs, N);

    const int WPB = 256;
    int grid_n = cdiv((long long)N * 32, WPB);

    // ---- layer 1 ----
    prop_c1_p1<<<grid_n, WPB>>>(xs, dis, edges, rs, t1, t1s, N);
    fused_l1<<<grid_n, WPB>>>(t1s, x, t1, dis, W1, bufA, xb, edges, rs, N);

    // ---- layer 2 (tf32 mma combine) ----
    prop_c16_p1<<<grid_n, WPB>>>(xb, dis, edges, rs, t1, tb, N);
    fused_l2_mma<<<cdiv(N, 16), 512>>>(tb, bufA, t1, dis, wbt2, bufB, xb, edges, rs, N);

    // ---- layer 3 (tf32 mma combine) + head ----
    prop_c32_p1<<<grid_n, WPB>>>(xb, dis, edges, rs, t1, tb, N);
    fused_l3_mma<<<cdiv(N, 16), 512>>>(tb, bufB, t1, dis, wbt3, W4,
                                       bufA, t2, edges, rs, N);

    // ---- layer 4 tail ----
    prop_csr_c4<<<grid_n, WPB>>>(t2, dis, edges, rs, bufB, N);
    prop2_final_k<<<grid_n, WPB>>>(bufB, bufA, dis, edges, rs, (float*)d_out, N);
}

// round 17
// speedup vs baseline: 1.0898x; 1.0064x over previous
#include <cuda_runtime.h>
#include <cuda_bf16.h>
#include <cstdint>

#define NMAX 100000
#define EMAX 3200000

// Scratch (device globals: allocation is forbidden).
__device__ float g_deg[NMAX];
__device__ float g_dis[NMAX];
__device__ float g_xs[NMAX];
__device__ int   g_cnt[NMAX];
__device__ int   g_rs[NMAX + 1];
__device__ int   g_cur[NMAX];
__device__ unsigned long long g_sstate[128];
__device__ uint2 g_edges[EMAX];         // {src, ea} sorted by dst
__device__ float g_bufA[NMAX * 64];     // layer-1 out (N*16) -> later part (N*2)
__device__ float g_bufB[NMAX * 64];     // layer-2 out (N*32) -> later zprop (N*4)
__device__ float g_t1[NMAX * 64];
__device__ float g_t1s[NMAX];
__device__ float g_t2[NMAX * 64];       // zpack (N*4)
__device__ __nv_bfloat16 g_xb[NMAX * 32];   // bf16 shadow (dis-scaled)
__device__ __nv_bfloat16 g_tb[NMAX * 32];   // bf16 shadow of t1 (dis-scaled)
__device__ unsigned g_wbt3[64 * 96];        // W3 as Bt[co][k], tf32 bits
__device__ unsigned g_wbt2[32 * 48];        // W2 as Bt[co][k], tf32 bits

static inline int cdiv(long long a, int b) { return (int)((a + b - 1) / b); }

__device__ __forceinline__ unsigned to_tf32(float v) {
    unsigned u;
    asm("cvt.rna.tf32.f32 %0, %1;" : "=r"(u) : "f"(v));
    return u;
}

// ===========================================================================
// Build phase
// ===========================================================================
__global__ void build_init_k(float* deg, int* cnt, unsigned long long* sstate,
                             const float* __restrict__ W3, const float* __restrict__ W2,
                             unsigned* __restrict__ wbt3, unsigned* __restrict__ wbt2,
                             int n) {
    int i = blockIdx.x * blockDim.x + threadIdx.x;
    if (i < n) { deg[i] = 0.f; cnt[i] = 0; }
    if (i < 128) sstate[i] = 0ULL;
    if (i < 64 * 96) {
        int co = i / 96, k = i % 96;
        wbt3[i] = to_tf32(W3[(k >> 5) * 2048 + (k & 31) * 64 + co]);
    }
    if (i < 32 * 48) {
        int co = i / 48, k = i % 48;
        wbt2[i] = to_tf32(W2[(k >> 4) * 512 + (k & 15) * 32 + co]);
    }
}

// cnt[dst[e]] += 1 only — dst stream only (deg moved into scatter)
__global__ void cnt_hist_k(const int* __restrict__ dst, int* __restrict__ cnt, int E) {
    int base = (blockIdx.x * blockDim.x + threadIdx.x) * 4;
    if (base + 3 < E) {
        int4 d = *reinterpret_cast<const int4*>(dst + base);
        atomicAdd(&cnt[d.x], 1);
        atomicAdd(&cnt[d.y], 1);
        atomicAdd(&cnt[d.z], 1);
        atomicAdd(&cnt[d.w], 1);
    } else {
        for (int e = base; e < E; e++) atomicAdd(&cnt[dst[e]], 1);
    }
}

__global__ void dis_k(const float* __restrict__ deg, const float* __restrict__ x,
                      float* __restrict__ dis, float* __restrict__ xs, int n) {
    int i = blockIdx.x * blockDim.x + threadIdx.x;
    if (i >= n) return;
    float d = deg[i];
    float r = d > 0.f ? rsqrtf(d) : 0.f;
    dis[i] = r;
    xs[i] = r * x[i];
}

#define SCAN_TPB 256
#define SCAN_ELEMS 1024

__global__ void scan_lookback_k(const int* __restrict__ cnt,
                                unsigned long long* __restrict__ sstate,
                                int* __restrict__ rs, int* __restrict__ cur, int n) {
    int b = blockIdx.x;
    int base = b * SCAN_ELEMS + threadIdx.x * 4;
    int c0 = 0, c1 = 0, c2 = 0, c3 = 0;
    if (base + 3 < n) {
        int4 v = *reinterpret_cast<const int4*>(cnt + base);
        c0 = v.x; c1 = v.y; c2 = v.z; c3 = v.w;
    } else {
        if (base + 0 < n) c0 = cnt[base + 0];
        if (base + 1 < n) c1 = cnt[base + 1];
        if (base + 2 < n) c2 = cnt[base + 2];
        if (base + 3 < n) c3 = cnt[base + 3];
    }
    int ts = c0 + c1 + c2 + c3;
    int lane = threadIdx.x & 31, wid = threadIdx.x >> 5;
    int inc = ts;
#pragma unroll
    for (int o = 1; o < 32; o <<= 1) {
        int v = __shfl_up_sync(0xffffffffu, inc, o);
        if (lane >= o) inc += v;
    }
    __shared__ int wsum[SCAN_TPB / 32];
    __shared__ int woff[SCAN_TPB / 32];
    __shared__ int s_base;
    __shared__ int s_total;
    if (lane == 31) wsum[wid] = inc;
    __syncthreads();
    if (threadIdx.x == 0) {
        int r = 0;
#pragma unroll
        for (int w = 0; w < SCAN_TPB / 32; w++) { woff[w] = r; r += wsum[w]; }
        s_total = r;
        atomicExch(&sstate[b], (1ULL << 62) | (unsigned)r);
        int excl = 0;
        for (int p = b - 1; p >= 0; ) {
            unsigned long long s;
            do { s = atomicAdd(&sstate[p], 0ULL); } while ((s >> 62) == 0);
            excl += (int)(unsigned)s;
            if ((s >> 62) == 2ULL) break;
            p--;
        }
        atomicExch(&sstate[b], (2ULL << 62) | (unsigned)(excl + r));
        s_base = excl;
    }
    __syncthreads();
    int r = s_base + (inc - ts) + woff[wid];
    if (base + 0 < n) { rs[base + 0] = r; cur[base + 0] = r; r += c0; }
    if (base + 1 < n) { rs[base + 1] = r; cur[base + 1] = r; r += c1; }
    if (base + 2 < n) { rs[base + 2] = r; cur[base + 2] = r; r += c2; }
    if (base + 3 < n) { rs[base + 3] = r; cur[base + 3] = r; r += c3; }
    if (b == gridDim.x - 1 && threadIdx.x == 0) rs[n] = s_base + s_total;
}

// 1 edge/thread; also accumulates deg[src] += ea (L2-resident atomic)
__global__ void scatter_k(const int* __restrict__ src, const int* __restrict__ dst,
                          const float* __restrict__ ea,
                          int* __restrict__ cur, float* __restrict__ deg,
                          uint2* __restrict__ ed, int E) {
    int e = blockIdx.x * blockDim.x + threadIdx.x;
    if (e >= E) return;
    int s = src[e];
    float w = ea[e];
    atomicAdd(&deg[s], w);
    int slot = atomicAdd(&cur[dst[e]], 1);
    ed[slot] = make_uint2((unsigned)s, __float_as_uint(w));
}

// ===========================================================================
// Layer 1
// ===========================================================================
__global__ void prop_c1_p1(const float* __restrict__ xs, const float* __restrict__ dis,
                           const uint2* __restrict__ ed, const int* __restrict__ rs,
                           float* __restrict__ out, float* __restrict__ outs, int N) {
    int warp = (blockIdx.x * blockDim.x + threadIdx.x) >> 5;
    int lane = threadIdx.x & 31;
    if (warp >= N) return;
    int beg = rs[warp], end = rs[warp + 1];
    float acc = 0.f;
    for (int j = beg + lane; j < end; j += 32) {
        uint2 e = ed[j];
        acc += __uint_as_float(e.y) * __ldg(xs + e.x);
    }
#pragma unroll
    for (int off = 16; off > 0; off >>= 1)
        acc += __shfl_down_sync(0xffffffffu, acc, off);
    if (lane == 0) {
        float di = dis[warp];
        float r = -di * acc;
        out[warp] = r;
        outs[warp] = di * r;
    }
}

__global__ void fused_l1(const float* __restrict__ t1s, const float* __restrict__ x,
                         const float* __restrict__ t1, const float* __restrict__ dis,
                         const float* __restrict__ W,
                         float* __restrict__ out, __nv_bfloat16* __restrict__ outb,
                         const uint2* __restrict__ ed, const int* __restrict__ rs, int N) {
    __shared__ float sW[48];
    if (threadIdx.x < 48) sW[threadIdx.x] = W[threadIdx.x];
    __syncthreads();
    int warp = (blockIdx.x * blockDim.x + threadIdx.x) >> 5;
    int lane = threadIdx.x & 31;
    if (warp >= N) return;
    int beg = rs[warp], end = rs[warp + 1];
    float acc = 0.f;
    for (int j = beg + lane; j < end; j += 32) {
        uint2 e = ed[j];
        acc += __uint_as_float(e.y) * __ldg(t1s + e.x);
    }
#pragma unroll
    for (int off = 16; off > 0; off >>= 1)
        acc += __shfl_xor_sync(0xffffffffu, acc, off);
    float di = dis[warp];
    float t2v = -di * acc;
    float a = x[warp];
    float b = t1[warp];
    if (lane < 16) {
        float d = 2.f * t2v - a;
        float r = fmaxf(a * sW[lane] + b * sW[16 + lane] + d * sW[32 + lane], 0.f);
        out[(size_t)warp * 16 + lane] = r;
        outb[(size_t)warp * 16 + lane] = __float2bfloat16_rn(di * r);
    }
}

// ===========================================================================
// Layer 2/3 pass-1 props (R14 bodies)
// ===========================================================================
__global__ void prop_c16_p1(const __nv_bfloat16* __restrict__ xb,
                            const float* __restrict__ dis,
                            const uint2* __restrict__ ed, const int* __restrict__ rs,
                            float* __restrict__ out, __nv_bfloat16* __restrict__ outb,
                            int N) {
    int warp = (blockIdx.x * blockDim.x + threadIdx.x) >> 5;
    int lane = threadIdx.x & 31;
    if (warp >= N) return;
    int grp = lane >> 3;
    int sub = lane & 7;
    int beg = rs[warp], end = rs[warp + 1];
    float ax = 0.f, ay = 0.f;
    int j = beg;
    for (; j + 16 <= end; j += 16) {
        uint2 e[4];
#pragma unroll
        for (int k = 0; k < 4; k++) e[k] = ed[j + k * 4 + grp];
        float2 f[4];
#pragma unroll
        for (int k = 0; k < 4; k++) {
            __nv_bfloat162 v = *reinterpret_cast<const __nv_bfloat162*>(
                xb + (size_t)e[k].x * 16 + sub * 2);
            f[k] = __bfloat1622float2(v);
        }
#pragma unroll
        for (int k = 0; k < 4; k++) {
            float w = __uint_as_float(e[k].y);
            ax = fmaf(w, f[k].x, ax);
            ay = fmaf(w, f[k].y, ay);
        }
    }
    for (; j < end; j += 4) {
        int idx = j + grp;
        if (idx < end) {
            uint2 e = ed[idx];
            __nv_bfloat162 v = *reinterpret_cast<const __nv_bfloat162*>(
                xb + (size_t)e.x * 16 + sub * 2);
            float2 f = __bfloat1622float2(v);
            float w = __uint_as_float(e.y);
            ax = fmaf(w, f.x, ax); ay = fmaf(w, f.y, ay);
        }
    }
    ax += __shfl_xor_sync(0xffffffffu, ax, 8);
    ay += __shfl_xor_sync(0xffffffffu, ay, 8);
    ax += __shfl_xor_sync(0xffffffffu, ax, 16);
    ay += __shfl_xor_sync(0xffffffffu, ay, 16);
    if (lane < 8) {
        float di = dis[warp];
        float2 r; r.x = -di * ax; r.y = -di * ay;
        *reinterpret_cast<float2*>(out + (size_t)warp * 16 + sub * 2) = r;
        float2 s; s.x = di * r.x; s.y = di * r.y;
        __nv_bfloat162 b = __float22bfloat162_rn(s);
        *reinterpret_cast<__nv_bfloat162*>(outb + (size_t)warp * 16 + sub * 2) = b;
    }
}

__global__ void prop_c32_p1(const __nv_bfloat16* __restrict__ xb,
                            const float* __restrict__ dis,
                            const uint2* __restrict__ ed, const int* __restrict__ rs,
                            float* __restrict__ out, __nv_bfloat16* __restrict__ outb,
                            int N) {
    int warp = (blockIdx.x * blockDim.x + threadIdx.x) >> 5;
    int lane = threadIdx.x & 31;
    if (warp >= N) return;
    int grp = lane >> 4;
    int sub = lane & 15;
    int beg = rs[warp], end = rs[warp + 1];
    float ax = 0.f, ay = 0.f;
    int j = beg;
    for (; j + 16 <= end; j += 16) {
        uint2 e[8];
#pragma unroll
        for (int k = 0; k < 8; k++) e[k] = ed[j + k * 2 + grp];
        float2 f[8];
#pragma unroll
        for (int k = 0; k < 8; k++) {
            __nv_bfloat162 v = *reinterpret_cast<const __nv_bfloat162*>(
                xb + (size_t)e[k].x * 32 + sub * 2);
            f[k] = __bfloat1622float2(v);
        }
#pragma unroll
        for (int k = 0; k < 8; k++) {
            float w = __uint_as_float(e[k].y);
            ax = fmaf(w, f[k].x, ax);
            ay = fmaf(w, f[k].y, ay);
        }
    }
    for (; j < end; j += 2) {
        int idx = j + grp;
        if (idx < end) {
            uint2 e = ed[idx];
            __nv_bfloat162 v = *reinterpret_cast<const __nv_bfloat162*>(
                xb + (size_t)e.x * 32 + sub * 2);
            float2 f = __bfloat1622float2(v);
            float w = __uint_as_float(e.y);
            ax = fmaf(w, f.x, ax); ay = fmaf(w, f.y, ay);
        }
    }
    ax += __shfl_xor_sync(0xffffffffu, ax, 16);
    ay += __shfl_xor_sync(0xffffffffu, ay, 16);
    if (lane < 16) {
        float di = dis[warp];
        float2 r; r.x = -di * ax; r.y = -di * ay;
        *reinterpret_cast<float2*>(out + (size_t)warp * 32 + sub * 2) = r;
        float2 s; s.x = di * r.x; s.y = di * r.y;
        __nv_bfloat162 b = __float22bfloat162_rn(s);
        *reinterpret_cast<__nv_bfloat162*>(outb + (size_t)warp * 32 + sub * 2) = b;
    }
}

// ===========================================================================
// Layer 2 fused: pass-2 gather + combine 16->32 via tf32 mma.
// ===========================================================================
#define AS2 52

__global__ void __launch_bounds__(512)
fused_l2_mma(const __nv_bfloat16* __restrict__ tb,
             const float* __restrict__ f0, const float* __restrict__ t1,
             const float* __restrict__ dis, const unsigned* __restrict__ wbt2,
             float* __restrict__ out, __nv_bfloat16* __restrict__ outb,
             const uint2* __restrict__ ed, const int* __restrict__ rs, int N) {
    __shared__ unsigned A_sm[16 * AS2];
    __shared__ unsigned Bt_sm[32 * AS2];
    __shared__ float h_sm[16 * 32];
    __shared__ float dis_sm[16];

    int tid = threadIdx.x;
    int wid = tid >> 5;
    int lane = tid & 31;
    int node = blockIdx.x * 16 + wid;

    for (int i = tid; i < 32 * 48; i += 512) {
        int co = i / 48, k = i % 48;
        Bt_sm[co * AS2 + k] = wbt2[i];
    }

    float di = 0.f;
    float t2x = 0.f, t2y = 0.f;
    if (node < N) {
        int grp = lane >> 3;
        int sub = lane & 7;
        int beg = rs[node], end = rs[node + 1];
        float ax = 0.f, ay = 0.f;
        int j = beg;
        for (; j + 16 <= end; j += 16) {
            uint2 e[4];
#pragma unroll
            for (int k = 0; k < 4; k++) e[k] = ed[j + k * 4 + grp];
            float2 f[4];
#pragma unroll
            for (int k = 0; k < 4; k++) {
                __nv_bfloat162 v = *reinterpret_cast<const __nv_bfloat162*>(
                    tb + (size_t)e[k].x * 16 + sub * 2);
                f[k] = __bfloat1622float2(v);
            }
#pragma unroll
            for (int k = 0; k < 4; k++) {
                float w = __uint_as_float(e[k].y);
                ax = fmaf(w, f[k].x, ax);
                ay = fmaf(w, f[k].y, ay);
            }
        }
        for (; j < end; j += 4) {
            int idx = j + grp;
            if (idx < end) {
                uint2 e = ed[idx];
                __nv_bfloat162 v = *reinterpret_cast<const __nv_bfloat162*>(
                    tb + (size_t)e.x * 16 + sub * 2);
                float2 f = __bfloat1622float2(v);
                float w = __uint_as_float(e.y);
                ax = fmaf(w, f.x, ax); ay = fmaf(w, f.y, ay);
            }
        }
        ax += __shfl_xor_sync(0xffffffffu, ax, 8);
        ay += __shfl_xor_sync(0xffffffffu, ay, 8);
        ax += __shfl_xor_sync(0xffffffffu, ax, 16);
        ay += __shfl_xor_sync(0xffffffffu, ay, 16);
        di = dis[node];
        t2x = -di * ax;
        t2y = -di * ay;
    }
    if (lane == 0) dis_sm[wid] = di;

    {
        int c = lane & 15;
        float a = 0.f, b = 0.f, dval = 0.f;
        if (node < N) {
            a = f0[(size_t)node * 16 + c];
            b = t1[(size_t)node * 16 + c];
            float tx = __shfl_sync(0xffffffffu, t2x, c >> 1);
            float ty = __shfl_sync(0xffffffffu, t2y, c >> 1);
            float t2c = (c & 1) ? ty : tx;
            dval = 2.f * t2c - a;
        }
        if (lane < 16) {
            A_sm[wid * AS2 + c] = to_tf32(a);
            A_sm[wid * AS2 + 16 + c] = to_tf32(b);
            A_sm[wid * AS2 + 32 + c] = to_tf32(dval);
        }
    }
    __syncthreads();

    if (wid < 4) {
        int row = lane >> 2;
        int qc = lane & 3;
        float c0 = 0.f, c1 = 0.f, c2 = 0.f, c3 = 0.f;
        const unsigned* Arow0 = A_sm + row * AS2;
        const unsigned* Arow1 = A_sm + (row + 8) * AS2;
        const unsigned* Brow = Bt_sm + (wid * 8 + row) * AS2;
#pragma unroll
        for (int kt = 0; kt < 6; kt++) {
            int k0 = kt * 8 + qc;
            unsigned a0 = Arow0[k0];
            unsigned a1 = Arow1[k0];
            unsigned a2 = Arow0[k0 + 4];
            unsigned a3 = Arow1[k0 + 4];
            unsigned b0 = Brow[k0];
            unsigned b1 = Brow[k0 + 4];
            asm volatile(
                "mma.sync.aligned.m16n8k8.row.col.f32.tf32.tf32.f32 "
                "{%0,%1,%2,%3}, {%4,%5,%6,%7}, {%8,%9}, {%0,%1,%2,%3};"
                : "+f"(c0), "+f"(c1), "+f"(c2), "+f"(c3)
                : "r"(a0), "r"(a1), "r"(a2), "r"(a3), "r"(b0), "r"(b1));
        }
        int col0 = wid * 8 + qc * 2;
        float2 v;
        v.x = fmaxf(c0, 0.f); v.y = fmaxf(c1, 0.f);
        *reinterpret_cast<float2*>(h_sm + row * 32 + col0) = v;
        v.x = fmaxf(c2, 0.f); v.y = fmaxf(c3, 0.f);
        *reinterpret_cast<float2*>(h_sm + (row + 8) * 32 + col0) = v;
    }
    __syncthreads();

    if (node >= N) return;
    float dw = dis_sm[wid];
    float h = h_sm[wid * 32 + lane];
    out[(size_t)node * 32 + lane] = h;
    outb[(size_t)node * 32 + lane] = __float2bfloat16_rn(dw * h);
}

// ===========================================================================
// Layer 3 fused: pass-2 gather + combine via tf32 mma + head GEMM.
// ===========================================================================
#define AS 100

__global__ void __launch_bounds__(512)
fused_l3_mma(const __nv_bfloat16* __restrict__ tb,
             const float* __restrict__ f0, const float* __restrict__ t1,
             const float* __restrict__ dis,
             const unsigned* __restrict__ wbt, const float* __restrict__ W4,
             float* __restrict__ part, float* __restrict__ zpack,
             const uint2* __restrict__ ed, const int* __restrict__ rs, int N) {
    __shared__ unsigned A_sm[16 * AS];
    __shared__ unsigned Bt_sm[64 * AS];
    __shared__ float h_sm[16 * 64];
    __shared__ float sW4[6 * 64];

    int tid = threadIdx.x;
    int wid = tid >> 5;
    int lane = tid & 31;
    int node = blockIdx.x * 16 + wid;

    for (int i = tid; i < 64 * 96; i += 512) {
        int co = i / 96, k = i % 96;
        Bt_sm[co * AS + k] = wbt[i];
    }
    for (int i = tid; i < 384; i += 512) {
        int k = i / 128, rem = i % 128, ci = rem / 2, co = rem % 2;
        sW4[(k * 2 + co) * 64 + ci] = W4[i];
    }

    float di = 0.f, a = 0.f, b = 0.f, dval = 0.f;
    if (node < N) {
        int grp = lane >> 4;
        int sub = lane & 15;
        int beg = rs[node], end = rs[node + 1];
        float ax = 0.f, ay = 0.f;
        int j = beg;
        for (; j + 16 <= end; j += 16) {
            uint2 e[8];
#pragma unroll
            for (int k = 0; k < 8; k++) e[k] = ed[j + k * 2 + grp];
            float2 f[8];
#pragma unroll
            for (int k = 0; k < 8; k++) {
                __nv_bfloat162 v = *reinterpret_cast<const __nv_bfloat162*>(
                    tb + (size_t)e[k].x * 32 + sub * 2);
                f[k] = __bfloat1622float2(v);
            }
#pragma unroll
            for (int k = 0; k < 8; k++) {
                float w = __uint_as_float(e[k].y);
                ax = fmaf(w, f[k].x, ax);
                ay = fmaf(w, f[k].y, ay);
            }
        }
        for (; j < end; j += 2) {
            int idx = j + grp;
            if (idx < end) {
                uint2 e = ed[idx];
                __nv_bfloat162 v = *reinterpret_cast<const __nv_bfloat162*>(
                    tb + (size_t)e.x * 32 + sub * 2);
                float2 f = __bfloat1622float2(v);
                float w = __uint_as_float(e.y);
                ax = fmaf(w, f.x, ax); ay = fmaf(w, f.y, ay);
            }
        }
        ax += __shfl_xor_sync(0xffffffffu, ax, 16);
        ay += __shfl_xor_sync(0xffffffffu, ay, 16);
        di = dis[node];
        float t2x = -di * ax;
        float t2y = -di * ay;
        float tx = __shfl_sync(0xffffffffu, t2x, lane >> 1);
        float ty = __shfl_sync(0xffffffffu, t2y, lane >> 1);
        float t2c = (lane & 1) ? ty : tx;
        a = f0[(size_t)node * 32 + lane];
        b = t1[(size_t)node * 32 + lane];
        dval = 2.f * t2c - a;
    }
    A_sm[wid * AS + lane] = to_tf32(a);
    A_sm[wid * AS + 32 + lane] = to_tf32(b);
    A_sm[wid * AS + 64 + lane] = to_tf32(dval);
    __syncthreads();

    if (wid < 8) {
        int row = lane >> 2;
        int qc = lane & 3;
        float c0 = 0.f, c1 = 0.f, c2 = 0.f, c3 = 0.f;
        const unsigned* Arow0 = A_sm + row * AS;
        const unsigned* Arow1 = A_sm + (row + 8) * AS;
        const unsigned* Brow = Bt_sm + (wid * 8 + row) * AS;
#pragma unroll
        for (int kt = 0; kt < 12; kt++) {
            int k0 = kt * 8 + qc;
            unsigned a0 = Arow0[k0];
            unsigned a1 = Arow1[k0];
            unsigned a2 = Arow0[k0 + 4];
            unsigned a3 = Arow1[k0 + 4];
            unsigned b0 = Brow[k0];
            unsigned b1 = Brow[k0 + 4];
            asm volatile(
                "mma.sync.aligned.m16n8k8.row.col.f32.tf32.tf32.f32 "
                "{%0,%1,%2,%3}, {%4,%5,%6,%7}, {%8,%9}, {%0,%1,%2,%3};"
                : "+f"(c0), "+f"(c1), "+f"(c2), "+f"(c3)
                : "r"(a0), "r"(a1), "r"(a2), "r"(a3), "r"(b0), "r"(b1));
        }
        int col0 = wid * 8 + qc * 2;
        float2 v;
        v.x = fmaxf(c0, 0.f); v.y = fmaxf(c1, 0.f);
        *reinterpret_cast<float2*>(h_sm + row * 64 + col0) = v;
        v.x = fmaxf(c2, 0.f); v.y = fmaxf(c3, 0.f);
        *reinterpret_cast<float2*>(h_sm + (row + 8) * 64 + col0) = v;
    }
    __syncthreads();

    if (node >= N) return;
    float h0 = h_sm[wid * 64 + lane];
    float h1 = h_sm[wid * 64 + lane + 32];
    float r[6];
#pragma unroll
    for (int m = 0; m < 6; m++) {
        const float* w = sW4 + m * 64;
        float racc = fmaf(h1, w[lane + 32], h0 * w[lane]);
#pragma unroll
        for (int off = 16; off > 0; off >>= 1)
            racc += __shfl_down_sync(0xffffffffu, racc, off);
        r[m] = racc;
    }
    if (lane == 0) {
        part[(size_t)node * 2 + 0] = r[0] - r[4];
        part[(size_t)node * 2 + 1] = r[1] - r[5];
        float4 z; z.x = di * r[2]; z.y = di * r[3]; z.z = di * r[4]; z.w = di * r[5];
        *reinterpret_cast<float4*>(zpack + (size_t)node * 4) = z;
    }
}

// ===========================================================================
// Layer-4 tail props
// ===========================================================================
__global__ void prop_csr_c4(const float* __restrict__ zs, const float* __restrict__ dis,
                            const uint2* __restrict__ ed, const int* __restrict__ rs,
                            float* __restrict__ out, int N) {
    int warp = (blockIdx.x * blockDim.x + threadIdx.x) >> 5;
    int lane = threadIdx.x & 31;
    if (warp >= N) return;
    int k = lane >> 2;
    int c = lane & 3;
    int beg = rs[warp], end = rs[warp + 1];
    float acc = 0.f;
    for (int j = beg + k; j < end; j += 8) {
        uint2 e = ed[j];
        acc = fmaf(__uint_as_float(e.y), __ldg(zs + (size_t)e.x * 4 + c), acc);
    }
#pragma unroll
    for (int off = 16; off >= 4; off >>= 1)
        acc += __shfl_down_sync(0xffffffffu, acc, off);
    if (lane < 4) {
        float di = dis[warp];
        float r = -di * acc;
        out[(size_t)warp * 4 + c] = (c < 2) ? r : di * r;
    }
}

__global__ void prop2_final_k(const float* __restrict__ t4, const float* __restrict__ part,
                              const float* __restrict__ dis,
                              const uint2* __restrict__ ed, const int* __restrict__ rs,
                              float* __restrict__ y, int N) {
    int warp = (blockIdx.x * blockDim.x + threadIdx.x) >> 5;
    int lane = threadIdx.x & 31;
    if (warp >= N) return;
    int k = lane >> 1;
    int c = lane & 1;
    int beg = rs[warp], end = rs[warp + 1];
    float acc = 0.f;
    for (int j = beg + k; j < end; j += 16) {
        uint2 e = ed[j];
        acc = fmaf(__uint_as_float(e.y), __ldg(t4 + (size_t)e.x * 4 + 2 + c), acc);
    }
#pragma unroll
    for (int off = 16; off >= 2; off >>= 1)
        acc += __shfl_down_sync(0xffffffffu, acc, off);
    if (lane < 2) {
        float w = -dis[warp] * acc;
        y[(size_t)warp * 2 + c] = part[(size_t)warp * 2 + c]
                                + t4[(size_t)warp * 4 + c] + 2.f * w;
    }
}

extern "C" void kernel_launch(void* const* d_in, const int* in_sizes, int n_in,
                              void* d_out, int out_size) {
    const float* x = (const float*)d_in[0];
    const int* edge_index = (const int*)d_in[1];
    const float* ea = (const float*)d_in[2];
    const float* W1 = (const float*)d_in[3];
    const float* W2 = (const float*)d_in[4];
    const float* W3 = (const float*)d_in[5];
    const float* W4 = (const float*)d_in[6];

    const int N = in_sizes[0];
    const int E = in_sizes[2];
    const int* src = edge_index;
    const int* dst = edge_index + E;

    float *deg, *dis, *xs, *bufA, *bufB, *t1, *t1s, *t2;
    int *cnt, *rs, *cur;
    unsigned long long* sstate;
    uint2* edges;
    __nv_bfloat16 *xb, *tb;
    unsigned *wbt3, *wbt2;
    cudaGetSymbolAddress((void**)&deg, g_deg);
    cudaGetSymbolAddress((void**)&dis, g_dis);
    cudaGetSymbolAddress((void**)&xs, g_xs);
    cudaGetSymbolAddress((void**)&cnt, g_cnt);
    cudaGetSymbolAddress((void**)&rs, g_rs);
    cudaGetSymbolAddress((void**)&cur, g_cur);
    cudaGetSymbolAddress((void**)&sstate, g_sstate);
    cudaGetSymbolAddress((void**)&edges, g_edges);
    cudaGetSymbolAddress((void**)&bufA, g_bufA);
    cudaGetSymbolAddress((void**)&bufB, g_bufB);
    cudaGetSymbolAddress((void**)&t1, g_t1);
    cudaGetSymbolAddress((void**)&t1s, g_t1s);
    cudaGetSymbolAddress((void**)&t2, g_t2);
    cudaGetSymbolAddress((void**)&xb, g_xb);
    cudaGetSymbolAddress((void**)&tb, g_tb);
    cudaGetSymbolAddress((void**)&wbt3, g_wbt3);
    cudaGetSymbolAddress((void**)&wbt2, g_wbt2);

    // ---- build CSR + dis + weight prep ----
    build_init_k<<<cdiv(N, 256), 256>>>(deg, cnt, sstate, W3, W2, wbt3, wbt2, N);
    cnt_hist_k<<<cdiv(cdiv(E, 4), 256), 256>>>(dst, cnt, E);
    int nb = cdiv(N, SCAN_ELEMS);
    scan_lookback_k<<<nb, SCAN_TPB>>>(cnt, sstate, rs, cur, N);
    scatter_k<<<cdiv(E, 256), 256>>>(src, dst, ea, cur, deg, edges, E);
    dis_k<<<cdiv(N, 256), 256>>>(deg, x, dis, xs, N);

    const int WPB = 256;
    int grid_n = cdiv((long long)N * 32, WPB);

    // ---- layer 1 ----
    prop_c1_p1<<<grid_n, WPB>>>(xs, dis, edges, rs, t1, t1s, N);
    fused_l1<<<grid_n, WPB>>>(t1s, x, t1, dis, W1, bufA, xb, edges, rs, N);

    // ---- layer 2 (tf32 mma combine) ----
    prop_c16_p1<<<grid_n, WPB>>>(xb, dis, edges, rs, t1, tb, N);
    fused_l2_mma<<<cdiv(N, 16), 512>>>(tb, bufA, t1, dis, wbt2, bufB, xb, edges, rs, N);

    // ---- layer 3 (tf32 mma combine) + head ----
    prop_c32_p1<<<grid_n, WPB>>>(xb, dis, edges, rs, t1, tb, N);
    fused_l3_mma<<<cdiv(N, 16), 512>>>(tb, bufB, t1, dis, wbt3, W4,
                                       bufA, t2, edges, rs, N);

    // ---- layer 4 tail ----
    prop_csr_c4<<<grid_n, WPB>>>(t2, dis, edges, rs, bufB, N);
    prop2_final_k<<<grid_n, WPB>>>(bufB, bufA, dis, edges, rs, (float*)d_out, N);
}